// round 1
// baseline (speedup 1.0000x reference)
#include <cuda_runtime.h>
#include <cuda_bf16.h>
#include <math.h>

// Problem constants
#define BB 32
#define HH 112
#define WW2 112
#define CC 96
#define NHH 3
#define WSZ 7
#define SHIFT 3
#define HID 384
#define NN 49          // tokens per window
#define HD 32          // head dim
#define NWIN 256       // windows per image (16*16)
#define TOK (BB*HH*WW2)  // 401408 tokens

// Scratch: x1 = shortcut + attn_out  (154 MB)
__device__ float g_x1[(size_t)TOK * CC];

// ---------------- smem layout (attention) ----------------
// s_x   : 52 rows * 97   (LN'd tokens, later reused for attn@V output)
// s_qkv : 52 rows * 289  (q|k|v per token)
// s_w   : 96 rows * 97   (weight chunk)
// s_attn: 3 heads * 52*50 (logits -> probs)
#define XS 97
#define QS 289
#define WSY 97
#define AS1 50
#define AHS (52*50)
#define SX_OFF   0
#define SQ_OFF   (52*97)
#define SW_OFF   (SQ_OFF + 52*289)
#define SA_OFF   (SW_OFF + 96*97)
#define ATTN_SMEM_FLOATS (SA_OFF + 3*AHS)

__global__ __launch_bounds__(256, 1)
void swin_attn_kernel(const float* __restrict__ x,
                      const float* __restrict__ attn_mask,
                      const int*   __restrict__ rel_index,
                      const float* __restrict__ n1g, const float* __restrict__ n1b,
                      const float* __restrict__ qkv_w, const float* __restrict__ qkv_b,
                      const float* __restrict__ proj_w, const float* __restrict__ proj_b,
                      const float* __restrict__ bias_table)
{
    extern __shared__ float sm[];
    float* s_x    = sm + SX_OFF;
    float* s_qkv  = sm + SQ_OFF;
    float* s_w    = sm + SW_OFF;
    float* s_attn = sm + SA_OFF;

    const int tid  = threadIdx.x;
    const int lane = tid & 31;
    const int warp = tid >> 5;

    const int widx = blockIdx.x;
    const int b  = widx >> 8;         // image
    const int w2 = widx & 255;        // window in image
    const int wh = w2 >> 4, ww = w2 & 15;

    // ---- 1. gather (with cyclic shift) + LayerNorm1 ----
    for (int n = warp; n < NN; n += 8) {
        const int i = n / WSZ, j = n % WSZ;
        int sy = wh * WSZ + i + SHIFT; if (sy >= HH)  sy -= HH;
        int sx = ww * WSZ + j + SHIFT; if (sx >= WW2) sx -= WW2;
        const float* xp = x + ((size_t)(b * 12544 + sy * WW2 + sx)) * CC;
        float v0 = xp[lane], v1 = xp[lane + 32], v2 = xp[lane + 64];
        float s  = v0 + v1 + v2;
        float sq = v0*v0 + v1*v1 + v2*v2;
        #pragma unroll
        for (int o = 16; o > 0; o >>= 1) {
            s  += __shfl_xor_sync(0xffffffffu, s,  o);
            sq += __shfl_xor_sync(0xffffffffu, sq, o);
        }
        const float mean = s * (1.f / 96.f);
        const float var  = sq * (1.f / 96.f) - mean * mean;
        const float rstd = rsqrtf(var + 1e-5f);
        s_x[n*XS + lane]      = (v0 - mean) * rstd * n1g[lane]      + n1b[lane];
        s_x[n*XS + lane + 32] = (v1 - mean) * rstd * n1g[lane + 32] + n1b[lane + 32];
        s_x[n*XS + lane + 64] = (v2 - mean) * rstd * n1g[lane + 64] + n1b[lane + 64];
    }
    // init attn logits with relative bias + window mask
    for (int idx = tid; idx < NHH*NN*NN; idx += 256) {
        const int h = idx / (NN*NN);
        const int r = idx - h * (NN*NN);
        const int n = r / NN, m = r - n * NN;
        s_attn[h*AHS + n*AS1 + m] =
            bias_table[rel_index[n*NN + m] * NHH + h] +
            attn_mask[((size_t)w2 * NN + n) * NN + m];
    }
    __syncthreads();

    // ---- 2. qkv GEMM in 3 chunks of 96 output dims ----
    for (int ch = 0; ch < 3; ch++) {
        for (int idx = tid; idx < 96*96; idx += 256) {
            const int r = idx / 96, c = idx - r * 96;
            s_w[r*WSY + c] = qkv_w[(ch*96 + r) * 96 + c];
        }
        __syncthreads();
        const float scale = (ch == 0) ? 0.17677669529663687f : 1.0f;
        for (int task = tid; task < 13*24; task += 256) {
            const int ng = task % 13, og = task / 13;
            float acc[4][4];
            #pragma unroll
            for (int a = 0; a < 4; a++)
                #pragma unroll
                for (int bq = 0; bq < 4; bq++) acc[a][bq] = 0.f;
            #pragma unroll 4
            for (int c = 0; c < 96; c++) {
                float xv[4], wv[4];
                #pragma unroll
                for (int mi = 0; mi < 4; mi++) xv[mi] = s_x[(ng*4 + mi)*XS + c];
                #pragma unroll
                for (int oi = 0; oi < 4; oi++) wv[oi] = s_w[(og*4 + oi)*WSY + c];
                #pragma unroll
                for (int mi = 0; mi < 4; mi++)
                    #pragma unroll
                    for (int oi = 0; oi < 4; oi++) acc[mi][oi] += xv[mi] * wv[oi];
            }
            #pragma unroll
            for (int mi = 0; mi < 4; mi++) {
                const int n = ng*4 + mi;
                if (n < NN) {
                    #pragma unroll
                    for (int oi = 0; oi < 4; oi++) {
                        const int o = og*4 + oi;
                        s_qkv[n*QS + ch*96 + o] = (acc[mi][oi] + qkv_b[ch*96 + o]) * scale;
                    }
                }
            }
        }
        __syncthreads();
    }

    // ---- 3. attention logits: attn += q . k ----
    for (int task = tid; task < NHH*NN*13; task += 256) {
        const int mg = task % 13;
        const int t2 = task / 13;
        const int n  = t2 % NN;
        const int h  = t2 / NN;
        float acc[4] = {0.f, 0.f, 0.f, 0.f};
        const float* qrow = s_qkv + n*QS + h*HD;
        #pragma unroll 8
        for (int d = 0; d < HD; d++) {
            const float qv = qrow[d];
            #pragma unroll
            for (int k = 0; k < 4; k++)
                acc[k] += qv * s_qkv[(mg*4 + k)*QS + 96 + h*HD + d];
        }
        #pragma unroll
        for (int k = 0; k < 4; k++) {
            const int m = mg*4 + k;
            if (m < NN) s_attn[h*AHS + n*AS1 + m] += acc[k];
        }
    }
    __syncthreads();

    // ---- 4. softmax (one warp per row) ----
    for (int r = warp; r < NHH*NN; r += 8) {
        const int h = r / NN, n = r % NN;
        float* row = s_attn + h*AHS + n*AS1;
        float a0 = (lane < NN)      ? row[lane]      : -1e30f;
        float a1 = (lane + 32 < NN) ? row[lane + 32] : -1e30f;
        float mx = fmaxf(a0, a1);
        #pragma unroll
        for (int o = 16; o > 0; o >>= 1) mx = fmaxf(mx, __shfl_xor_sync(0xffffffffu, mx, o));
        float e0 = (lane < NN)      ? __expf(a0 - mx) : 0.f;
        float e1 = (lane + 32 < NN) ? __expf(a1 - mx) : 0.f;
        float s = e0 + e1;
        #pragma unroll
        for (int o = 16; o > 0; o >>= 1) s += __shfl_xor_sync(0xffffffffu, s, o);
        const float inv = 1.f / s;
        if (lane < NN)      row[lane]      = e0 * inv;
        if (lane + 32 < NN) row[lane + 32] = e1 * inv;
    }
    __syncthreads();

    // ---- 5. out = attn @ v  (write into s_x, which is free now) ----
    for (int task = tid; task < 13*24; task += 256) {
        const int ng = task % 13, cg = task / 13;
        const int h  = (cg*4) >> 5;
        float acc[4][4];
        #pragma unroll
        for (int a = 0; a < 4; a++)
            #pragma unroll
            for (int bq = 0; bq < 4; bq++) acc[a][bq] = 0.f;
        for (int m = 0; m < NN; m++) {
            float vv[4];
            #pragma unroll
            for (int ci = 0; ci < 4; ci++) vv[ci] = s_qkv[m*QS + 192 + cg*4 + ci];
            #pragma unroll
            for (int mi = 0; mi < 4; mi++) {
                const float av = s_attn[h*AHS + (ng*4 + mi)*AS1 + m];
                #pragma unroll
                for (int ci = 0; ci < 4; ci++) acc[mi][ci] += av * vv[ci];
            }
        }
        #pragma unroll
        for (int mi = 0; mi < 4; mi++) {
            const int n = ng*4 + mi;
            if (n < NN) {
                #pragma unroll
                for (int ci = 0; ci < 4; ci++)
                    s_x[n*XS + cg*4 + ci] = acc[mi][ci];
            }
        }
    }
    // stage proj weights (s_w free after qkv chunks)
    for (int idx = tid; idx < 96*96; idx += 256) {
        const int r = idx / 96, c = idx - r * 96;
        s_w[r*WSY + c] = proj_w[idx];
    }
    __syncthreads();

    // ---- 6. proj + residual, scatter with reverse shift ----
    for (int task = tid; task < 13*24; task += 256) {
        const int ng = task % 13, og = task / 13;
        float acc[4][4];
        #pragma unroll
        for (int a = 0; a < 4; a++)
            #pragma unroll
            for (int bq = 0; bq < 4; bq++) acc[a][bq] = 0.f;
        #pragma unroll 4
        for (int c = 0; c < 96; c++) {
            float xv[4], wv[4];
            #pragma unroll
            for (int mi = 0; mi < 4; mi++) xv[mi] = s_x[(ng*4 + mi)*XS + c];
            #pragma unroll
            for (int oi = 0; oi < 4; oi++) wv[oi] = s_w[(og*4 + oi)*WSY + c];
            #pragma unroll
            for (int mi = 0; mi < 4; mi++)
                #pragma unroll
                for (int oi = 0; oi < 4; oi++) acc[mi][oi] += xv[mi] * wv[oi];
        }
        #pragma unroll
        for (int mi = 0; mi < 4; mi++) {
            const int n = ng*4 + mi;
            if (n < NN) {
                const int i = n / WSZ, j = n % WSZ;
                int oy = wh * WSZ + i + SHIFT; if (oy >= HH)  oy -= HH;
                int ox = ww * WSZ + j + SHIFT; if (ox >= WW2) ox -= WW2;
                const size_t base = ((size_t)(b * 12544 + oy * WW2 + ox)) * CC + og*4;
                const float4 res = *reinterpret_cast<const float4*>(x + base);
                float4 o4;
                o4.x = acc[mi][0] + proj_b[og*4 + 0] + res.x;
                o4.y = acc[mi][1] + proj_b[og*4 + 1] + res.y;
                o4.z = acc[mi][2] + proj_b[og*4 + 2] + res.z;
                o4.w = acc[mi][3] + proj_b[og*4 + 3] + res.w;
                *reinterpret_cast<float4*>(g_x1 + base) = o4;
            }
        }
    }
}

// ---------------- MLP kernel: 64 tokens / block ----------------
// s_t : 64*97   LN'd tokens
// s_h : 64*385  hidden (gelu output)
// s_w : 6240    weight chunk (max(64*97, 96*65))
#define TS 97
#define HS 385
#define MT_OFF 0
#define MH_OFF (64*97)
#define MW_OFF (MH_OFF + 64*385)
#define MLP_SMEM_FLOATS (MW_OFF + 6240)

__global__ __launch_bounds__(256, 1)
void swin_mlp_kernel(const float* __restrict__ n2g, const float* __restrict__ n2b,
                     const float* __restrict__ fc1w, const float* __restrict__ fc1b,
                     const float* __restrict__ fc2w, const float* __restrict__ fc2b,
                     float* __restrict__ out)
{
    extern __shared__ float sm[];
    float* s_t = sm + MT_OFF;
    float* s_h = sm + MH_OFF;
    float* s_w = sm + MW_OFF;

    const int tid  = threadIdx.x;
    const int lane = tid & 31;
    const int warp = tid >> 5;
    const int tok0 = blockIdx.x * 64;

    // ---- LN2 ----
    for (int n = warp; n < 64; n += 8) {
        const float* xp = g_x1 + (size_t)(tok0 + n) * CC;
        float v0 = xp[lane], v1 = xp[lane + 32], v2 = xp[lane + 64];
        float s  = v0 + v1 + v2;
        float sq = v0*v0 + v1*v1 + v2*v2;
        #pragma unroll
        for (int o = 16; o > 0; o >>= 1) {
            s  += __shfl_xor_sync(0xffffffffu, s,  o);
            sq += __shfl_xor_sync(0xffffffffu, sq, o);
        }
        const float mean = s * (1.f / 96.f);
        const float var  = sq * (1.f / 96.f) - mean * mean;
        const float rstd = rsqrtf(var + 1e-5f);
        s_t[n*TS + lane]      = (v0 - mean) * rstd * n2g[lane]      + n2b[lane];
        s_t[n*TS + lane + 32] = (v1 - mean) * rstd * n2g[lane + 32] + n2b[lane + 32];
        s_t[n*TS + lane + 64] = (v2 - mean) * rstd * n2g[lane + 64] + n2b[lane + 64];
    }
    __syncthreads();

    // ---- fc1 + GELU, 6 chunks of 64 output rows ----
    const int ng1 = tid & 15, og1 = tid >> 4;   // 16x16 thread grid, 4x4 tile each
    for (int ch = 0; ch < 6; ch++) {
        for (int idx = tid; idx < 64*96; idx += 256) {
            const int r = idx / 96, c = idx - r * 96;
            s_w[r*TS + c] = fc1w[(ch*64 + r) * 96 + c];
        }
        __syncthreads();
        float acc[4][4];
        #pragma unroll
        for (int a = 0; a < 4; a++)
            #pragma unroll
            for (int bq = 0; bq < 4; bq++) acc[a][bq] = 0.f;
        #pragma unroll 4
        for (int c = 0; c < 96; c++) {
            float tv[4], wv[4];
            #pragma unroll
            for (int mi = 0; mi < 4; mi++) tv[mi] = s_t[(ng1*4 + mi)*TS + c];
            #pragma unroll
            for (int oi = 0; oi < 4; oi++) wv[oi] = s_w[(og1*4 + oi)*TS + c];
            #pragma unroll
            for (int mi = 0; mi < 4; mi++)
                #pragma unroll
                for (int oi = 0; oi < 4; oi++) acc[mi][oi] += tv[mi] * wv[oi];
        }
        #pragma unroll
        for (int mi = 0; mi < 4; mi++) {
            #pragma unroll
            for (int oi = 0; oi < 4; oi++) {
                const int o = og1*4 + oi;
                const float h = acc[mi][oi] + fc1b[ch*64 + o];
                const float g = 0.5f * h * (1.f + erff(h * 0.70710678118654752f));
                s_h[(ng1*4 + mi)*HS + ch*64 + o] = g;
            }
        }
        __syncthreads();
    }

    // ---- fc2 (+bias +residual) ----
    const int ng2 = tid & 15, og2 = tid >> 4;   // 4 tokens x 6 outs per thread
    float acc2[4][6];
    #pragma unroll
    for (int a = 0; a < 4; a++)
        #pragma unroll
        for (int bq = 0; bq < 6; bq++) acc2[a][bq] = 0.f;
    for (int kc = 0; kc < 6; kc++) {
        for (int idx = tid; idx < 96*64; idx += 256) {
            const int o = idx / 64, kk = idx - o * 64;
            s_w[o*65 + kk] = fc2w[o*384 + kc*64 + kk];
        }
        __syncthreads();
        #pragma unroll 4
        for (int kk = 0; kk < 64; kk++) {
            float hv[4], wv[6];
            #pragma unroll
            for (int mi = 0; mi < 4; mi++) hv[mi] = s_h[(ng2*4 + mi)*HS + kc*64 + kk];
            #pragma unroll
            for (int oi = 0; oi < 6; oi++) wv[oi] = s_w[(og2*6 + oi)*65 + kk];
            #pragma unroll
            for (int mi = 0; mi < 4; mi++)
                #pragma unroll
                for (int oi = 0; oi < 6; oi++) acc2[mi][oi] += hv[mi] * wv[oi];
        }
        __syncthreads();
    }
    #pragma unroll
    for (int mi = 0; mi < 4; mi++) {
        const size_t tok = (size_t)tok0 + ng2*4 + mi;
        #pragma unroll
        for (int oi = 0; oi < 6; oi++) {
            const int o = og2*6 + oi;
            out[tok*CC + o] = acc2[mi][oi] + fc2b[o] + g_x1[tok*CC + o];
        }
    }
}

extern "C" void kernel_launch(void* const* d_in, const int* in_sizes, int n_in,
                              void* d_out, int out_size)
{
    const float* x          = (const float*)d_in[0];
    const float* attn_mask  = (const float*)d_in[1];
    const int*   rel_index  = (const int*)  d_in[2];
    const float* n1g        = (const float*)d_in[3];
    const float* n1b        = (const float*)d_in[4];
    const float* qkv_w      = (const float*)d_in[5];
    const float* qkv_b      = (const float*)d_in[6];
    const float* proj_w     = (const float*)d_in[7];
    const float* proj_b     = (const float*)d_in[8];
    const float* bias_table = (const float*)d_in[9];
    const float* n2g        = (const float*)d_in[10];
    const float* n2b        = (const float*)d_in[11];
    const float* fc1w       = (const float*)d_in[12];
    const float* fc1b       = (const float*)d_in[13];
    const float* fc2w       = (const float*)d_in[14];
    const float* fc2b       = (const float*)d_in[15];
    float* out = (float*)d_out;

    const size_t attn_smem = ATTN_SMEM_FLOATS * sizeof(float);
    const size_t mlp_smem  = MLP_SMEM_FLOATS  * sizeof(float);
    cudaFuncSetAttribute(swin_attn_kernel, cudaFuncAttributeMaxDynamicSharedMemorySize, (int)attn_smem);
    cudaFuncSetAttribute(swin_mlp_kernel,  cudaFuncAttributeMaxDynamicSharedMemorySize, (int)mlp_smem);

    swin_attn_kernel<<<BB * NWIN, 256, attn_smem>>>(
        x, attn_mask, rel_index, n1g, n1b, qkv_w, qkv_b, proj_w, proj_b, bias_table);
    swin_mlp_kernel<<<TOK / 64, 256, mlp_smem>>>(
        n2g, n2b, fc1w, fc1b, fc2w, fc2b, out);
}

// round 2
// speedup vs baseline: 1.3284x; 1.3284x over previous
#include <cuda_runtime.h>
#include <cuda_bf16.h>
#include <math.h>

// Problem constants
#define BB 32
#define HH 112
#define WW2 112
#define CC 96
#define NHH 3
#define WSZ 7
#define SHIFT 3
#define HID 384
#define NN 49          // tokens per window
#define HD 32          // head dim
#define NWIN 256       // windows per image (16*16)
#define TOK (BB*HH*WW2)  // 401408 tokens

// Scratch: x1 = shortcut + attn_out
__device__ float g_x1[(size_t)TOK * CC];

// ---------------- attention smem layout ----------------
// floats : s_x  52*98, s_attn 3*49*50
// bf16   : s_qkv 52*292, s_w 96*100
#define XS 98
#define QS 292
#define WST 100
#define AS1 50
#define AHS (49*50)
#define ATT_FLOATS (52*XS + NHH*AHS)
#define ATT_SMEM_BYTES (ATT_FLOATS*4 + (52*QS + 96*WST)*2)

__device__ __forceinline__ float2 bf2f(const __nv_bfloat16* p) {
    return __bfloat1622float2(*reinterpret_cast<const __nv_bfloat162*>(p));
}

__global__ __launch_bounds__(256, 2)
void swin_attn_kernel(const float* __restrict__ x,
                      const float* __restrict__ attn_mask,
                      const int*   __restrict__ rel_index,
                      const float* __restrict__ n1g, const float* __restrict__ n1b,
                      const float* __restrict__ qkv_w, const float* __restrict__ qkv_b,
                      const float* __restrict__ proj_w, const float* __restrict__ proj_b,
                      const float* __restrict__ bias_table)
{
    extern __shared__ float sm[];
    float* s_x    = sm;
    float* s_attn = sm + 52*XS;
    __nv_bfloat16* s_qkv = reinterpret_cast<__nv_bfloat16*>(sm + ATT_FLOATS);
    __nv_bfloat16* s_w   = s_qkv + 52*QS;

    const int tid  = threadIdx.x;
    const int lane = tid & 31;
    const int warp = tid >> 5;

    const int widx = blockIdx.x;
    const int b  = widx >> 8;
    const int w2 = widx & 255;
    const int wh = w2 >> 4, ww = w2 & 15;

    // ---- 1. gather (with cyclic shift) + LayerNorm1 ----
    for (int n = warp; n < NN; n += 8) {
        const int i = n / WSZ, j = n % WSZ;
        int sy = wh * WSZ + i + SHIFT; if (sy >= HH)  sy -= HH;
        int sx = ww * WSZ + j + SHIFT; if (sx >= WW2) sx -= WW2;
        const float* xp = x + ((size_t)(b * 12544 + sy * WW2 + sx)) * CC;
        float v0 = xp[lane], v1 = xp[lane + 32], v2 = xp[lane + 64];
        float s  = v0 + v1 + v2;
        float sq = v0*v0 + v1*v1 + v2*v2;
        #pragma unroll
        for (int o = 16; o > 0; o >>= 1) {
            s  += __shfl_xor_sync(0xffffffffu, s,  o);
            sq += __shfl_xor_sync(0xffffffffu, sq, o);
        }
        const float mean = s * (1.f / 96.f);
        const float var  = sq * (1.f / 96.f) - mean * mean;
        const float rstd = rsqrtf(var + 1e-5f);
        s_x[n*XS + lane]      = (v0 - mean) * rstd * n1g[lane]      + n1b[lane];
        s_x[n*XS + lane + 32] = (v1 - mean) * rstd * n1g[lane + 32] + n1b[lane + 32];
        s_x[n*XS + lane + 64] = (v2 - mean) * rstd * n1g[lane + 64] + n1b[lane + 64];
    }
    // zero the 3 pad token rows of qkv (read by logits loop)
    for (int idx = tid; idx < 3*QS; idx += 256)
        s_qkv[(NN + idx / QS)*QS + (idx % QS)] = __float2bfloat16(0.f);
    // init attn logits with relative bias + window mask
    for (int idx = tid; idx < NHH*NN*NN; idx += 256) {
        const int h = idx / (NN*NN);
        const int r = idx - h * (NN*NN);
        const int n = r / NN, m = r - n * NN;
        s_attn[h*AHS + n*AS1 + m] =
            bias_table[rel_index[n*NN + m] * NHH + h] +
            attn_mask[((size_t)w2 * NN + n) * NN + m];
    }
    __syncthreads();

    // ---- 2. qkv GEMM in 3 chunks of 96 output dims ----
    for (int ch = 0; ch < 3; ch++) {
        for (int idx = tid; idx < 96*96; idx += 256) {
            const int r = idx / 96, c = idx - r * 96;
            s_w[r*WST + c] = __float2bfloat16(qkv_w[(ch*96 + r) * 96 + c]);
        }
        __syncthreads();
        const float scale = (ch == 0) ? 0.17677669529663687f : 1.0f;
        for (int task = tid; task < 13*24; task += 256) {
            const int ng = task % 13, og = task / 13;
            float acc[4][4];
            #pragma unroll
            for (int a = 0; a < 4; a++)
                #pragma unroll
                for (int bq = 0; bq < 4; bq++) acc[a][bq] = 0.f;
            #pragma unroll 4
            for (int c = 0; c < 96; c += 2) {
                float2 xv[4], wv[4];
                #pragma unroll
                for (int mi = 0; mi < 4; mi++)
                    xv[mi] = *reinterpret_cast<const float2*>(&s_x[(ng*4 + mi)*XS + c]);
                #pragma unroll
                for (int oi = 0; oi < 4; oi++)
                    wv[oi] = bf2f(&s_w[(og*4 + oi)*WST + c]);
                #pragma unroll
                for (int mi = 0; mi < 4; mi++)
                    #pragma unroll
                    for (int oi = 0; oi < 4; oi++) {
                        acc[mi][oi] += xv[mi].x * wv[oi].x;
                        acc[mi][oi] += xv[mi].y * wv[oi].y;
                    }
            }
            #pragma unroll
            for (int mi = 0; mi < 4; mi++) {
                const int n = ng*4 + mi;
                if (n < NN) {
                    #pragma unroll
                    for (int oi = 0; oi < 4; oi++) {
                        const int o = og*4 + oi;
                        s_qkv[n*QS + ch*96 + o] =
                            __float2bfloat16((acc[mi][oi] + qkv_b[ch*96 + o]) * scale);
                    }
                }
            }
        }
        __syncthreads();
    }

    // ---- 3. attention logits: attn += q . k ----
    for (int task = tid; task < NHH*NN*13; task += 256) {
        const int mg = task % 13;
        const int t2 = task / 13;
        const int n  = t2 % NN;
        const int h  = t2 / NN;
        float acc[4] = {0.f, 0.f, 0.f, 0.f};
        const __nv_bfloat16* qrow = s_qkv + n*QS + h*HD;
        const int kb = 96 + h*HD;
        #pragma unroll 4
        for (int d = 0; d < HD; d += 2) {
            float2 q2 = bf2f(qrow + d);
            #pragma unroll
            for (int k = 0; k < 4; k++) {
                float2 k2 = bf2f(&s_qkv[(mg*4 + k)*QS + kb + d]);
                acc[k] += q2.x * k2.x;
                acc[k] += q2.y * k2.y;
            }
        }
        #pragma unroll
        for (int k = 0; k < 4; k++) {
            const int m = mg*4 + k;
            if (m < NN) s_attn[h*AHS + n*AS1 + m] += acc[k];
        }
    }
    __syncthreads();

    // ---- 4. softmax (one warp per row) ----
    for (int r = warp; r < NHH*NN; r += 8) {
        const int h = r / NN, n = r % NN;
        float* row = s_attn + h*AHS + n*AS1;
        float a0 = (lane < NN)      ? row[lane]      : -1e30f;
        float a1 = (lane + 32 < NN) ? row[lane + 32] : -1e30f;
        float mx = fmaxf(a0, a1);
        #pragma unroll
        for (int o = 16; o > 0; o >>= 1) mx = fmaxf(mx, __shfl_xor_sync(0xffffffffu, mx, o));
        float e0 = (lane < NN)      ? __expf(a0 - mx) : 0.f;
        float e1 = (lane + 32 < NN) ? __expf(a1 - mx) : 0.f;
        float s = e0 + e1;
        #pragma unroll
        for (int o = 16; o > 0; o >>= 1) s += __shfl_xor_sync(0xffffffffu, s, o);
        const float inv = 1.f / s;
        if (lane < NN)      row[lane]      = e0 * inv;
        if (lane + 32 < NN) row[lane + 32] = e1 * inv;
    }
    __syncthreads();

    // ---- 5. out = attn @ v  (write into s_x, which is free now) ----
    for (int task = tid; task < 13*24; task += 256) {
        const int ng = task % 13, cg = task / 13;
        const int h  = (cg*4) >> 5;
        float acc[4][4];
        #pragma unroll
        for (int a = 0; a < 4; a++)
            #pragma unroll
            for (int bq = 0; bq < 4; bq++) acc[a][bq] = 0.f;
        for (int m = 0; m < NN; m++) {
            float2 v01 = bf2f(&s_qkv[m*QS + 192 + cg*4]);
            float2 v23 = bf2f(&s_qkv[m*QS + 192 + cg*4 + 2]);
            const float vv[4] = {v01.x, v01.y, v23.x, v23.y};
            #pragma unroll
            for (int mi = 0; mi < 4; mi++) {
                const int n = ng*4 + mi;
                const float av = (n < NN) ? s_attn[h*AHS + n*AS1 + m] : 0.f;
                #pragma unroll
                for (int ci = 0; ci < 4; ci++) acc[mi][ci] += av * vv[ci];
            }
        }
        #pragma unroll
        for (int mi = 0; mi < 4; mi++) {
            const int n = ng*4 + mi;
            if (n < NN) {
                #pragma unroll
                for (int ci = 0; ci < 4; ci++)
                    s_x[n*XS + cg*4 + ci] = acc[mi][ci];
            }
        }
    }
    // stage proj weights (s_w free after qkv chunks)
    for (int idx = tid; idx < 96*96; idx += 256) {
        const int r = idx / 96, c = idx - r * 96;
        s_w[r*WST + c] = __float2bfloat16(proj_w[idx]);
    }
    __syncthreads();

    // ---- 6. proj + residual, scatter with reverse shift ----
    for (int task = tid; task < 13*24; task += 256) {
        const int ng = task % 13, og = task / 13;
        float acc[4][4];
        #pragma unroll
        for (int a = 0; a < 4; a++)
            #pragma unroll
            for (int bq = 0; bq < 4; bq++) acc[a][bq] = 0.f;
        #pragma unroll 4
        for (int c = 0; c < 96; c += 2) {
            float2 xv[4], wv[4];
            #pragma unroll
            for (int mi = 0; mi < 4; mi++)
                xv[mi] = *reinterpret_cast<const float2*>(&s_x[(ng*4 + mi)*XS + c]);
            #pragma unroll
            for (int oi = 0; oi < 4; oi++)
                wv[oi] = bf2f(&s_w[(og*4 + oi)*WST + c]);
            #pragma unroll
            for (int mi = 0; mi < 4; mi++)
                #pragma unroll
                for (int oi = 0; oi < 4; oi++) {
                    acc[mi][oi] += xv[mi].x * wv[oi].x;
                    acc[mi][oi] += xv[mi].y * wv[oi].y;
                }
        }
        #pragma unroll
        for (int mi = 0; mi < 4; mi++) {
            const int n = ng*4 + mi;
            if (n < NN) {
                const int i = n / WSZ, j = n % WSZ;
                int oy = wh * WSZ + i + SHIFT; if (oy >= HH)  oy -= HH;
                int ox = ww * WSZ + j + SHIFT; if (ox >= WW2) ox -= WW2;
                const size_t base = ((size_t)(b * 12544 + oy * WW2 + ox)) * CC + og*4;
                const float4 res = *reinterpret_cast<const float4*>(x + base);
                float4 o4;
                o4.x = acc[mi][0] + proj_b[og*4 + 0] + res.x;
                o4.y = acc[mi][1] + proj_b[og*4 + 1] + res.y;
                o4.z = acc[mi][2] + proj_b[og*4 + 2] + res.z;
                o4.w = acc[mi][3] + proj_b[og*4 + 3] + res.w;
                *reinterpret_cast<float4*>(g_x1 + base) = o4;
            }
        }
    }
}

// ---------------- MLP kernel: 64 tokens / block ----------------
// floats : s_t 64*98, s_w 6336
// bf16   : s_h 64*392
#define TS 98
#define HS 392
#define MLP_FLOATS (64*TS + 6336)
#define MLP_SMEM_BYTES (MLP_FLOATS*4 + 64*HS*2)

__global__ __launch_bounds__(256, 2)
void swin_mlp_kernel(const float* __restrict__ n2g, const float* __restrict__ n2b,
                     const float* __restrict__ fc1w, const float* __restrict__ fc1b,
                     const float* __restrict__ fc2w, const float* __restrict__ fc2b,
                     float* __restrict__ out)
{
    extern __shared__ float sm[];
    float* s_t = sm;
    float* s_w = sm + 64*TS;
    __nv_bfloat16* s_h = reinterpret_cast<__nv_bfloat16*>(sm + MLP_FLOATS);

    const int tid  = threadIdx.x;
    const int lane = tid & 31;
    const int warp = tid >> 5;
    const int tok0 = blockIdx.x * 64;

    // ---- LN2 ----
    for (int n = warp; n < 64; n += 8) {
        const float* xp = g_x1 + (size_t)(tok0 + n) * CC;
        float v0 = xp[lane], v1 = xp[lane + 32], v2 = xp[lane + 64];
        float s  = v0 + v1 + v2;
        float sq = v0*v0 + v1*v1 + v2*v2;
        #pragma unroll
        for (int o = 16; o > 0; o >>= 1) {
            s  += __shfl_xor_sync(0xffffffffu, s,  o);
            sq += __shfl_xor_sync(0xffffffffu, sq, o);
        }
        const float mean = s * (1.f / 96.f);
        const float var  = sq * (1.f / 96.f) - mean * mean;
        const float rstd = rsqrtf(var + 1e-5f);
        s_t[n*TS + lane]      = (v0 - mean) * rstd * n2g[lane]      + n2b[lane];
        s_t[n*TS + lane + 32] = (v1 - mean) * rstd * n2g[lane + 32] + n2b[lane + 32];
        s_t[n*TS + lane + 64] = (v2 - mean) * rstd * n2g[lane + 64] + n2b[lane + 64];
    }
    __syncthreads();

    // ---- fc1 + GELU, 6 chunks of 64 output rows ----
    const int ng1 = tid & 15, og1 = tid >> 4;   // 16x16 thread grid, 4x4 tile each
    for (int ch = 0; ch < 6; ch++) {
        for (int idx = tid; idx < 64*96; idx += 256) {
            const int r = idx / 96, c = idx - r * 96;
            s_w[r*TS + c] = fc1w[(ch*64 + r) * 96 + c];
        }
        __syncthreads();
        float acc[4][4];
        #pragma unroll
        for (int a = 0; a < 4; a++)
            #pragma unroll
            for (int bq = 0; bq < 4; bq++) acc[a][bq] = 0.f;
        #pragma unroll 4
        for (int c = 0; c < 96; c += 2) {
            float2 tv[4], wv[4];
            #pragma unroll
            for (int mi = 0; mi < 4; mi++)
                tv[mi] = *reinterpret_cast<const float2*>(&s_t[(ng1*4 + mi)*TS + c]);
            #pragma unroll
            for (int oi = 0; oi < 4; oi++)
                wv[oi] = *reinterpret_cast<const float2*>(&s_w[(og1*4 + oi)*TS + c]);
            #pragma unroll
            for (int mi = 0; mi < 4; mi++)
                #pragma unroll
                for (int oi = 0; oi < 4; oi++) {
                    acc[mi][oi] += tv[mi].x * wv[oi].x;
                    acc[mi][oi] += tv[mi].y * wv[oi].y;
                }
        }
        #pragma unroll
        for (int mi = 0; mi < 4; mi++) {
            #pragma unroll
            for (int oi = 0; oi < 4; oi++) {
                const int o = og1*4 + oi;
                const float h = acc[mi][oi] + fc1b[ch*64 + o];
                const float g = 0.5f * h * (1.f + erff(h * 0.70710678118654752f));
                s_h[(ng1*4 + mi)*HS + ch*64 + o] = __float2bfloat16(g);
            }
        }
        __syncthreads();
    }

    // ---- fc2 (+bias +residual) ----
    const int ng2 = tid & 15, og2 = tid >> 4;   // 4 tokens x 6 outs per thread
    float acc2[4][6];
    #pragma unroll
    for (int a = 0; a < 4; a++)
        #pragma unroll
        for (int bq = 0; bq < 6; bq++) acc2[a][bq] = 0.f;
    for (int kc = 0; kc < 6; kc++) {
        for (int idx = tid; idx < 96*64; idx += 256) {
            const int o = idx / 64, kk = idx - o * 64;
            s_w[o*66 + kk] = fc2w[o*384 + kc*64 + kk];
        }
        __syncthreads();
        #pragma unroll 4
        for (int kk = 0; kk < 64; kk += 2) {
            float2 hv[4], wv[6];
            #pragma unroll
            for (int mi = 0; mi < 4; mi++)
                hv[mi] = bf2f(&s_h[(ng2*4 + mi)*HS + kc*64 + kk]);
            #pragma unroll
            for (int oi = 0; oi < 6; oi++)
                wv[oi] = *reinterpret_cast<const float2*>(&s_w[(og2*6 + oi)*66 + kk]);
            #pragma unroll
            for (int mi = 0; mi < 4; mi++)
                #pragma unroll
                for (int oi = 0; oi < 6; oi++) {
                    acc2[mi][oi] += hv[mi].x * wv[oi].x;
                    acc2[mi][oi] += hv[mi].y * wv[oi].y;
                }
        }
        __syncthreads();
    }
    #pragma unroll
    for (int mi = 0; mi < 4; mi++) {
        const size_t tok = (size_t)tok0 + ng2*4 + mi;
        #pragma unroll
        for (int oi = 0; oi < 6; oi++) {
            const int o = og2*6 + oi;
            out[tok*CC + o] = acc2[mi][oi] + fc2b[o] + g_x1[tok*CC + o];
        }
    }
}

extern "C" void kernel_launch(void* const* d_in, const int* in_sizes, int n_in,
                              void* d_out, int out_size)
{
    const float* x          = (const float*)d_in[0];
    const float* attn_mask  = (const float*)d_in[1];
    const int*   rel_index  = (const int*)  d_in[2];
    const float* n1g        = (const float*)d_in[3];
    const float* n1b        = (const float*)d_in[4];
    const float* qkv_w      = (const float*)d_in[5];
    const float* qkv_b      = (const float*)d_in[6];
    const float* proj_w     = (const float*)d_in[7];
    const float* proj_b     = (const float*)d_in[8];
    const float* bias_table = (const float*)d_in[9];
    const float* n2g        = (const float*)d_in[10];
    const float* n2b        = (const float*)d_in[11];
    const float* fc1w       = (const float*)d_in[12];
    const float* fc1b       = (const float*)d_in[13];
    const float* fc2w       = (const float*)d_in[14];
    const float* fc2b       = (const float*)d_in[15];
    float* out = (float*)d_out;

    cudaFuncSetAttribute(swin_attn_kernel, cudaFuncAttributeMaxDynamicSharedMemorySize,
                         (int)ATT_SMEM_BYTES);
    cudaFuncSetAttribute(swin_mlp_kernel,  cudaFuncAttributeMaxDynamicSharedMemorySize,
                         (int)MLP_SMEM_BYTES);

    swin_attn_kernel<<<BB * NWIN, 256, ATT_SMEM_BYTES>>>(
        x, attn_mask, rel_index, n1g, n1b, qkv_w, qkv_b, proj_w, proj_b, bias_table);
    swin_mlp_kernel<<<TOK / 64, 256, MLP_SMEM_BYTES>>>(
        n2g, n2b, fc1w, fc1b, fc2w, fc2b, out);
}

// round 13
// speedup vs baseline: 2.0343x; 1.5314x over previous
#include <cuda_runtime.h>
#include <cuda_bf16.h>
#include <math.h>
#include <cstdint>

// Problem constants
#define BB 32
#define HH 112
#define WW2 112
#define CC 96
#define NHH 3
#define WSZ 7
#define SHIFT 3
#define HID 384
#define NN 49
#define HD 32
#define NWIN 256
#define TOK (BB*HH*WW2)

// Scratch: x1 = shortcut + attn_out
__device__ float g_x1[(size_t)TOK * CC];

__device__ __forceinline__ float2 bf2f(const __nv_bfloat16* p) {
    return __bfloat1622float2(*reinterpret_cast<const __nv_bfloat162*>(p));
}

// Warp-level bf16 MMA (m16n8k16) - supported on base sm_103 target (HMMA)
__device__ __forceinline__ void mma16816(float* d, const uint32_t* a, const uint32_t* b) {
    asm volatile(
        "mma.sync.aligned.m16n8k16.row.col.f32.bf16.bf16.f32 "
        "{%0,%1,%2,%3}, {%4,%5,%6,%7}, {%8,%9}, {%0,%1,%2,%3};\n"
        : "+f"(d[0]), "+f"(d[1]), "+f"(d[2]), "+f"(d[3])
        : "r"(a[0]), "r"(a[1]), "r"(a[2]), "r"(a[3]), "r"(b[0]), "r"(b[1]));
}

// ============================================================================
// Attention kernel (unchanged from round 2 - passing)
// ============================================================================
#define XS 98
#define QS 292
#define WST 100
#define AS1 50
#define AHS (49*50)
#define ATT_FLOATS (52*XS + NHH*AHS)
#define ATT_SMEM_BYTES (ATT_FLOATS*4 + (52*QS + 96*WST)*2)

__global__ __launch_bounds__(256, 2)
void swin_attn_kernel(const float* __restrict__ x,
                      const float* __restrict__ attn_mask,
                      const int*   __restrict__ rel_index,
                      const float* __restrict__ n1g, const float* __restrict__ n1b,
                      const float* __restrict__ qkv_w, const float* __restrict__ qkv_b,
                      const float* __restrict__ proj_w, const float* __restrict__ proj_b,
                      const float* __restrict__ bias_table)
{
    extern __shared__ float sm[];
    float* s_x    = sm;
    float* s_attn = sm + 52*XS;
    __nv_bfloat16* s_qkv = reinterpret_cast<__nv_bfloat16*>(sm + ATT_FLOATS);
    __nv_bfloat16* s_w   = s_qkv + 52*QS;

    const int tid  = threadIdx.x;
    const int lane = tid & 31;
    const int warp = tid >> 5;

    const int widx = blockIdx.x;
    const int b  = widx >> 8;
    const int w2 = widx & 255;
    const int wh = w2 >> 4, ww = w2 & 15;

    for (int n = warp; n < NN; n += 8) {
        const int i = n / WSZ, j = n % WSZ;
        int sy = wh * WSZ + i + SHIFT; if (sy >= HH)  sy -= HH;
        int sx = ww * WSZ + j + SHIFT; if (sx >= WW2) sx -= WW2;
        const float* xp = x + ((size_t)(b * 12544 + sy * WW2 + sx)) * CC;
        float v0 = xp[lane], v1 = xp[lane + 32], v2 = xp[lane + 64];
        float s  = v0 + v1 + v2;
        float sq = v0*v0 + v1*v1 + v2*v2;
        #pragma unroll
        for (int o = 16; o > 0; o >>= 1) {
            s  += __shfl_xor_sync(0xffffffffu, s,  o);
            sq += __shfl_xor_sync(0xffffffffu, sq, o);
        }
        const float mean = s * (1.f / 96.f);
        const float var  = sq * (1.f / 96.f) - mean * mean;
        const float rstd = rsqrtf(var + 1e-5f);
        s_x[n*XS + lane]      = (v0 - mean) * rstd * n1g[lane]      + n1b[lane];
        s_x[n*XS + lane + 32] = (v1 - mean) * rstd * n1g[lane + 32] + n1b[lane + 32];
        s_x[n*XS + lane + 64] = (v2 - mean) * rstd * n1g[lane + 64] + n1b[lane + 64];
    }
    for (int idx = tid; idx < 3*QS; idx += 256)
        s_qkv[(NN + idx / QS)*QS + (idx % QS)] = __float2bfloat16(0.f);
    for (int idx = tid; idx < NHH*NN*NN; idx += 256) {
        const int h = idx / (NN*NN);
        const int r = idx - h * (NN*NN);
        const int n = r / NN, m = r - n * NN;
        s_attn[h*AHS + n*AS1 + m] =
            bias_table[rel_index[n*NN + m] * NHH + h] +
            attn_mask[((size_t)w2 * NN + n) * NN + m];
    }
    __syncthreads();

    for (int ch = 0; ch < 3; ch++) {
        for (int idx = tid; idx < 96*96; idx += 256) {
            const int r = idx / 96, c = idx - r * 96;
            s_w[r*WST + c] = __float2bfloat16(qkv_w[(ch*96 + r) * 96 + c]);
        }
        __syncthreads();
        const float scale = (ch == 0) ? 0.17677669529663687f : 1.0f;
        for (int task = tid; task < 13*24; task += 256) {
            const int ng = task % 13, og = task / 13;
            float acc[4][4];
            #pragma unroll
            for (int a = 0; a < 4; a++)
                #pragma unroll
                for (int bq = 0; bq < 4; bq++) acc[a][bq] = 0.f;
            #pragma unroll 4
            for (int c = 0; c < 96; c += 2) {
                float2 xv[4], wv[4];
                #pragma unroll
                for (int mi = 0; mi < 4; mi++)
                    xv[mi] = *reinterpret_cast<const float2*>(&s_x[(ng*4 + mi)*XS + c]);
                #pragma unroll
                for (int oi = 0; oi < 4; oi++)
                    wv[oi] = bf2f(&s_w[(og*4 + oi)*WST + c]);
                #pragma unroll
                for (int mi = 0; mi < 4; mi++)
                    #pragma unroll
                    for (int oi = 0; oi < 4; oi++) {
                        acc[mi][oi] += xv[mi].x * wv[oi].x;
                        acc[mi][oi] += xv[mi].y * wv[oi].y;
                    }
            }
            #pragma unroll
            for (int mi = 0; mi < 4; mi++) {
                const int n = ng*4 + mi;
                if (n < NN) {
                    #pragma unroll
                    for (int oi = 0; oi < 4; oi++) {
                        const int o = og*4 + oi;
                        s_qkv[n*QS + ch*96 + o] =
                            __float2bfloat16((acc[mi][oi] + qkv_b[ch*96 + o]) * scale);
                    }
                }
            }
        }
        __syncthreads();
    }

    for (int task = tid; task < NHH*NN*13; task += 256) {
        const int mg = task % 13;
        const int t2 = task / 13;
        const int n  = t2 % NN;
        const int h  = t2 / NN;
        float acc[4] = {0.f, 0.f, 0.f, 0.f};
        const __nv_bfloat16* qrow = s_qkv + n*QS + h*HD;
        const int kb = 96 + h*HD;
        #pragma unroll 4
        for (int d = 0; d < HD; d += 2) {
            float2 q2 = bf2f(qrow + d);
            #pragma unroll
            for (int k = 0; k < 4; k++) {
                float2 k2 = bf2f(&s_qkv[(mg*4 + k)*QS + kb + d]);
                acc[k] += q2.x * k2.x;
                acc[k] += q2.y * k2.y;
            }
        }
        #pragma unroll
        for (int k = 0; k < 4; k++) {
            const int m = mg*4 + k;
            if (m < NN) s_attn[h*AHS + n*AS1 + m] += acc[k];
        }
    }
    __syncthreads();

    for (int r = warp; r < NHH*NN; r += 8) {
        const int h = r / NN, n = r % NN;
        float* row = s_attn + h*AHS + n*AS1;
        float a0 = (lane < NN)      ? row[lane]      : -1e30f;
        float a1 = (lane + 32 < NN) ? row[lane + 32] : -1e30f;
        float mx = fmaxf(a0, a1);
        #pragma unroll
        for (int o = 16; o > 0; o >>= 1) mx = fmaxf(mx, __shfl_xor_sync(0xffffffffu, mx, o));
        float e0 = (lane < NN)      ? __expf(a0 - mx) : 0.f;
        float e1 = (lane + 32 < NN) ? __expf(a1 - mx) : 0.f;
        float s = e0 + e1;
        #pragma unroll
        for (int o = 16; o > 0; o >>= 1) s += __shfl_xor_sync(0xffffffffu, s, o);
        const float inv = 1.f / s;
        if (lane < NN)      row[lane]      = e0 * inv;
        if (lane + 32 < NN) row[lane + 32] = e1 * inv;
    }
    __syncthreads();

    for (int task = tid; task < 13*24; task += 256) {
        const int ng = task % 13, cg = task / 13;
        const int h  = (cg*4) >> 5;
        float acc[4][4];
        #pragma unroll
        for (int a = 0; a < 4; a++)
            #pragma unroll
            for (int bq = 0; bq < 4; bq++) acc[a][bq] = 0.f;
        for (int m = 0; m < NN; m++) {
            float2 v01 = bf2f(&s_qkv[m*QS + 192 + cg*4]);
            float2 v23 = bf2f(&s_qkv[m*QS + 192 + cg*4 + 2]);
            const float vv[4] = {v01.x, v01.y, v23.x, v23.y};
            #pragma unroll
            for (int mi = 0; mi < 4; mi++) {
                const int n = ng*4 + mi;
                const float av = (n < NN) ? s_attn[h*AHS + n*AS1 + m] : 0.f;
                #pragma unroll
                for (int ci = 0; ci < 4; ci++) acc[mi][ci] += av * vv[ci];
            }
        }
        #pragma unroll
        for (int mi = 0; mi < 4; mi++) {
            const int n = ng*4 + mi;
            if (n < NN) {
                #pragma unroll
                for (int ci = 0; ci < 4; ci++)
                    s_x[n*XS + cg*4 + ci] = acc[mi][ci];
            }
        }
    }
    for (int idx = tid; idx < 96*96; idx += 256) {
        const int r = idx / 96, c = idx - r * 96;
        s_w[r*WST + c] = __float2bfloat16(proj_w[idx]);
    }
    __syncthreads();

    for (int task = tid; task < 13*24; task += 256) {
        const int ng = task % 13, og = task / 13;
        float acc[4][4];
        #pragma unroll
        for (int a = 0; a < 4; a++)
            #pragma unroll
            for (int bq = 0; bq < 4; bq++) acc[a][bq] = 0.f;
        #pragma unroll 4
        for (int c = 0; c < 96; c += 2) {
            float2 xv[4], wv[4];
            #pragma unroll
            for (int mi = 0; mi < 4; mi++)
                xv[mi] = *reinterpret_cast<const float2*>(&s_x[(ng*4 + mi)*XS + c]);
            #pragma unroll
            for (int oi = 0; oi < 4; oi++)
                wv[oi] = bf2f(&s_w[(og*4 + oi)*WST + c]);
            #pragma unroll
            for (int mi = 0; mi < 4; mi++)
                #pragma unroll
                for (int oi = 0; oi < 4; oi++) {
                    acc[mi][oi] += xv[mi].x * wv[oi].x;
                    acc[mi][oi] += xv[mi].y * wv[oi].y;
                }
        }
        #pragma unroll
        for (int mi = 0; mi < 4; mi++) {
            const int n = ng*4 + mi;
            if (n < NN) {
                const int i = n / WSZ, j = n % WSZ;
                int oy = wh * WSZ + i + SHIFT; if (oy >= HH)  oy -= HH;
                int ox = ww * WSZ + j + SHIFT; if (ox >= WW2) ox -= WW2;
                const size_t base = ((size_t)(b * 12544 + oy * WW2 + ox)) * CC + og*4;
                const float4 res = *reinterpret_cast<const float4*>(x + base);
                float4 o4;
                o4.x = acc[mi][0] + proj_b[og*4 + 0] + res.x;
                o4.y = acc[mi][1] + proj_b[og*4 + 1] + res.y;
                o4.z = acc[mi][2] + proj_b[og*4 + 2] + res.z;
                o4.w = acc[mi][3] + proj_b[og*4 + 3] + res.w;
                *reinterpret_cast<float4*>(g_x1 + base) = o4;
            }
        }
    }
}

// ============================================================================
// MLP kernel: warp-level mma.sync bf16 (HMMA), 128 tokens per CTA
//   A  [128][104] bf16  (LN'd tokens; cols 96..103 pad, never read)
//   H  [128][392] bf16  (GELU output; cols 384..391 pad, never read)
//   W  region: W1 [384][104] bf16, then reused as W2 [96][392] bf16
// ============================================================================
#define AP 104
#define HP 392
#define MSM_A 0
#define MSM_H (128*AP*2)                    // 26624
#define MSM_W (MSM_H + 128*HP*2)            // 126976
#define MLP_SMEM_TOTAL (MSM_W + 384*AP*2)   // 206848 bytes

__global__ __launch_bounds__(256, 1)
void swin_mlp_mma(const float* __restrict__ n2g, const float* __restrict__ n2b,
                  const float* __restrict__ fc1w, const float* __restrict__ fc1b,
                  const float* __restrict__ fc2w, const float* __restrict__ fc2b,
                  float* __restrict__ out)
{
    extern __shared__ char smem[];
    __nv_bfloat16* sA = reinterpret_cast<__nv_bfloat16*>(smem + MSM_A);
    __nv_bfloat16* sH = reinterpret_cast<__nv_bfloat16*>(smem + MSM_H);
    __nv_bfloat16* sW = reinterpret_cast<__nv_bfloat16*>(smem + MSM_W);

    const int tid  = threadIdx.x;
    const int lane = tid & 31;
    const int warp = tid >> 5;
    const int gid  = lane >> 2;     // 0..7
    const int tig  = lane & 3;      // 0..3
    const int tok0 = blockIdx.x * 128;
    const int m0   = warp * 16;

    // ---- LN2 -> A tile (bf16) ----
    for (int n = warp; n < 128; n += 8) {
        const float* xp = g_x1 + (size_t)(tok0 + n) * CC;
        float v0 = xp[lane], v1 = xp[lane + 32], v2 = xp[lane + 64];
        float s  = v0 + v1 + v2;
        float sq = v0*v0 + v1*v1 + v2*v2;
        #pragma unroll
        for (int o = 16; o > 0; o >>= 1) {
            s  += __shfl_xor_sync(0xffffffffu, s,  o);
            sq += __shfl_xor_sync(0xffffffffu, sq, o);
        }
        const float mean = s * (1.f / 96.f);
        const float var  = sq * (1.f / 96.f) - mean * mean;
        const float rstd = rsqrtf(var + 1e-5f);
        sA[n*AP + lane]      = __float2bfloat16((v0 - mean) * rstd * n2g[lane]      + n2b[lane]);
        sA[n*AP + lane + 32] = __float2bfloat16((v1 - mean) * rstd * n2g[lane + 32] + n2b[lane + 32]);
        sA[n*AP + lane + 64] = __float2bfloat16((v2 - mean) * rstd * n2g[lane + 64] + n2b[lane + 64]);
    }
    // ---- stage W1 [384][96] -> sW [384][104] bf16 ----
    for (int p = tid; p < 384*48; p += 256) {
        const int r = p / 48, c = (p % 48) * 2;
        const float2 wv = *reinterpret_cast<const float2*>(fc1w + r*96 + c);
        *reinterpret_cast<__nv_bfloat162*>(&sW[r*AP + c]) = __floats2bfloat162_rn(wv.x, wv.y);
    }
    __syncthreads();

    // ---- GEMM1: C[128x384] = A[128x96] @ W1^T ; per-warp 16 rows, 3 n-chunks of 128 ----
    for (int nc = 0; nc < 3; nc++) {
        const int n0 = nc * 128;
        float acc[16][4];
        #pragma unroll
        for (int t = 0; t < 16; t++) {
            acc[t][0] = 0.f; acc[t][1] = 0.f; acc[t][2] = 0.f; acc[t][3] = 0.f;
        }
        #pragma unroll
        for (int ks = 0; ks < 6; ks++) {
            const int k = ks*16 + 2*tig;
            uint32_t a[4];
            a[0] = *reinterpret_cast<const uint32_t*>(&sA[(m0 + gid    )*AP + k]);
            a[1] = *reinterpret_cast<const uint32_t*>(&sA[(m0 + gid + 8)*AP + k]);
            a[2] = *reinterpret_cast<const uint32_t*>(&sA[(m0 + gid    )*AP + k + 8]);
            a[3] = *reinterpret_cast<const uint32_t*>(&sA[(m0 + gid + 8)*AP + k + 8]);
            #pragma unroll
            for (int nt = 0; nt < 16; nt++) {
                const int n = n0 + nt*8 + gid;
                uint32_t b[2];
                b[0] = *reinterpret_cast<const uint32_t*>(&sW[n*AP + k]);
                b[1] = *reinterpret_cast<const uint32_t*>(&sW[n*AP + k + 8]);
                mma16816(acc[nt], a, b);
            }
        }
        // epilogue: bias + GELU -> H (bf16)
        #pragma unroll
        for (int nt = 0; nt < 16; nt++) {
            const int n = n0 + nt*8 + 2*tig;
            const float b0 = fc1b[n], b1 = fc1b[n + 1];
            float h0 = acc[nt][0] + b0, h1 = acc[nt][1] + b1;
            float h2 = acc[nt][2] + b0, h3 = acc[nt][3] + b1;
            h0 = 0.5f * h0 * (1.f + erff(h0 * 0.70710678118654752f));
            h1 = 0.5f * h1 * (1.f + erff(h1 * 0.70710678118654752f));
            h2 = 0.5f * h2 * (1.f + erff(h2 * 0.70710678118654752f));
            h3 = 0.5f * h3 * (1.f + erff(h3 * 0.70710678118654752f));
            *reinterpret_cast<__nv_bfloat162*>(&sH[(m0 + gid    )*HP + n]) = __floats2bfloat162_rn(h0, h1);
            *reinterpret_cast<__nv_bfloat162*>(&sH[(m0 + gid + 8)*HP + n]) = __floats2bfloat162_rn(h2, h3);
        }
    }
    __syncthreads();

    // ---- stage W2 [96][384] -> sW [96][392] bf16 (overwrites W1) ----
    for (int p = tid; p < 96*192; p += 256) {
        const int r = p / 192, c = (p % 192) * 2;
        const float2 wv = *reinterpret_cast<const float2*>(fc2w + r*384 + c);
        *reinterpret_cast<__nv_bfloat162*>(&sW[r*HP + c]) = __floats2bfloat162_rn(wv.x, wv.y);
    }
    __syncthreads();

    // ---- GEMM2: C[128x96] = H[128x384] @ W2^T ; per-warp 16 rows x 96 cols ----
    {
        float acc[12][4];
        #pragma unroll
        for (int t = 0; t < 12; t++) {
            acc[t][0] = 0.f; acc[t][1] = 0.f; acc[t][2] = 0.f; acc[t][3] = 0.f;
        }
        for (int ks = 0; ks < 24; ks++) {
            const int k = ks*16 + 2*tig;
            uint32_t a[4];
            a[0] = *reinterpret_cast<const uint32_t*>(&sH[(m0 + gid    )*HP + k]);
            a[1] = *reinterpret_cast<const uint32_t*>(&sH[(m0 + gid + 8)*HP + k]);
            a[2] = *reinterpret_cast<const uint32_t*>(&sH[(m0 + gid    )*HP + k + 8]);
            a[3] = *reinterpret_cast<const uint32_t*>(&sH[(m0 + gid + 8)*HP + k + 8]);
            #pragma unroll
            for (int nt = 0; nt < 12; nt++) {
                const int n = nt*8 + gid;
                uint32_t b[2];
                b[0] = *reinterpret_cast<const uint32_t*>(&sW[n*HP + k]);
                b[1] = *reinterpret_cast<const uint32_t*>(&sW[n*HP + k + 8]);
                mma16816(acc[nt], a, b);
            }
        }
        // epilogue: bias + residual -> out
        #pragma unroll
        for (int nt = 0; nt < 12; nt++) {
            const int n = nt*8 + 2*tig;
            const float b0 = fc2b[n], b1 = fc2b[n + 1];
            const size_t r0 = (size_t)(tok0 + m0 + gid)     * CC + n;
            const size_t r1 = (size_t)(tok0 + m0 + gid + 8) * CC + n;
            const float2 x0 = *reinterpret_cast<const float2*>(g_x1 + r0);
            const float2 x1 = *reinterpret_cast<const float2*>(g_x1 + r1);
            float2 o0, o1;
            o0.x = acc[nt][0] + b0 + x0.x;  o0.y = acc[nt][1] + b1 + x0.y;
            o1.x = acc[nt][2] + b0 + x1.x;  o1.y = acc[nt][3] + b1 + x1.y;
            *reinterpret_cast<float2*>(out + r0) = o0;
            *reinterpret_cast<float2*>(out + r1) = o1;
        }
    }
}

extern "C" void kernel_launch(void* const* d_in, const int* in_sizes, int n_in,
                              void* d_out, int out_size)
{
    const float* x          = (const float*)d_in[0];
    const float* attn_mask  = (const float*)d_in[1];
    const int*   rel_index  = (const int*)  d_in[2];
    const float* n1g        = (const float*)d_in[3];
    const float* n1b        = (const float*)d_in[4];
    const float* qkv_w      = (const float*)d_in[5];
    const float* qkv_b      = (const float*)d_in[6];
    const float* proj_w     = (const float*)d_in[7];
    const float* proj_b     = (const float*)d_in[8];
    const float* bias_table = (const float*)d_in[9];
    const float* n2g        = (const float*)d_in[10];
    const float* n2b        = (const float*)d_in[11];
    const float* fc1w       = (const float*)d_in[12];
    const float* fc1b       = (const float*)d_in[13];
    const float* fc2w       = (const float*)d_in[14];
    const float* fc2b       = (const float*)d_in[15];
    float* out = (float*)d_out;

    cudaFuncSetAttribute(swin_attn_kernel, cudaFuncAttributeMaxDynamicSharedMemorySize,
                         (int)ATT_SMEM_BYTES);
    cudaFuncSetAttribute(swin_mlp_mma, cudaFuncAttributeMaxDynamicSharedMemorySize,
                         (int)MLP_SMEM_TOTAL);

    swin_attn_kernel<<<BB * NWIN, 256, ATT_SMEM_BYTES>>>(
        x, attn_mask, rel_index, n1g, n1b, qkv_w, qkv_b, proj_w, proj_b, bias_table);
    swin_mlp_mma<<<TOK / 128, 256, MLP_SMEM_TOTAL>>>(
        n2g, n2b, fc1w, fc1b, fc2w, fc2b, out);
}

// round 15
// speedup vs baseline: 2.7813x; 1.3672x over previous
#include <cuda_runtime.h>
#include <cuda_bf16.h>
#include <math.h>
#include <cstdint>

// Problem constants
#define BB 32
#define HH 112
#define WW2 112
#define CC 96
#define NHH 3
#define WSZ 7
#define SHIFT 3
#define HID 384
#define NN 49
#define HD 32
#define NWIN 256
#define TOK (BB*HH*WW2)

// Scratch: x1 = shortcut + attn_out
__device__ float g_x1[(size_t)TOK * CC];

// Warp-level bf16 MMA (m16n8k16) - base sm_103 target (HMMA)
__device__ __forceinline__ void mma16816(float* d, const uint32_t* a, const uint32_t* b) {
    asm volatile(
        "mma.sync.aligned.m16n8k16.row.col.f32.bf16.bf16.f32 "
        "{%0,%1,%2,%3}, {%4,%5,%6,%7}, {%8,%9}, {%0,%1,%2,%3};\n"
        : "+f"(d[0]), "+f"(d[1]), "+f"(d[2]), "+f"(d[3])
        : "r"(a[0]), "r"(a[1]), "r"(a[2]), "r"(a[3]), "r"(b[0]), "r"(b[1]));
}
__device__ __forceinline__ uint32_t packbf(float x, float y) {
    __nv_bfloat162 t = __floats2bfloat162_rn(x, y);
    return *reinterpret_cast<uint32_t*>(&t);
}

// ============================================================================
// Attention kernel: mma.sync per 49-token window (padded to 64 rows)
// smem bf16 tiles:
//   sX  [64][104]  LN'd tokens -> later attn output (A for qkv & proj)
//   sQ  [64][104], sK [64][104]   (q scaled; [tok][dim])
//   sVt [96][72]   V transposed [dim][tok]
//   sBM [3][64][72] bias+mask (padded m cols = -30000)
//   sW  [144][104] weight chunk (qkv staged 2x144; proj 96 rows)
// ============================================================================
#define MP 64
#define XP 104
#define VTP 72
#define BMP 72
#define ASM_X  0
#define ASM_Q  (ASM_X + MP*XP*2)
#define ASM_K  (ASM_Q + MP*XP*2)
#define ASM_VT (ASM_K + MP*XP*2)
#define ASM_BM (ASM_VT + 96*VTP*2)
#define ASM_W  (ASM_BM + NHH*MP*BMP*2)
#define ATT_SMEM_BYTES (ASM_W + 144*XP*2)   // 111360

__global__ __launch_bounds__(256, 2)
void swin_attn_mma(const float* __restrict__ x,
                   const float* __restrict__ attn_mask,
                   const int*   __restrict__ rel_index,
                   const float* __restrict__ n1g, const float* __restrict__ n1b,
                   const float* __restrict__ qkv_w, const float* __restrict__ qkv_b,
                   const float* __restrict__ proj_w, const float* __restrict__ proj_b,
                   const float* __restrict__ bias_table)
{
    extern __shared__ char smem[];
    __nv_bfloat16* sX  = reinterpret_cast<__nv_bfloat16*>(smem + ASM_X);
    __nv_bfloat16* sQ  = reinterpret_cast<__nv_bfloat16*>(smem + ASM_Q);
    __nv_bfloat16* sK  = reinterpret_cast<__nv_bfloat16*>(smem + ASM_K);
    __nv_bfloat16* sVt = reinterpret_cast<__nv_bfloat16*>(smem + ASM_VT);
    __nv_bfloat16* sBM = reinterpret_cast<__nv_bfloat16*>(smem + ASM_BM);
    __nv_bfloat16* sW  = reinterpret_cast<__nv_bfloat16*>(smem + ASM_W);

    const int tid  = threadIdx.x;
    const int lane = tid & 31;
    const int warp = tid >> 5;
    const int gid  = lane >> 2;   // 0..7
    const int tig  = lane & 3;    // 0..3

    const int widx = blockIdx.x;
    const int b  = widx >> 8;
    const int w2 = widx & 255;
    const int wh = w2 >> 4, ww = w2 & 15;

    // ---- phase 0a: gather + LN1 -> sX (bf16), one warp per token ----
    for (int n = warp; n < NN; n += 8) {
        const int i = n / WSZ, j = n % WSZ;
        int sy = wh * WSZ + i + SHIFT; if (sy >= HH)  sy -= HH;
        int sx = ww * WSZ + j + SHIFT; if (sx >= WW2) sx -= WW2;
        const float* xp = x + ((size_t)(b * 12544 + sy * WW2 + sx)) * CC;
        float v0 = xp[lane], v1 = xp[lane + 32], v2 = xp[lane + 64];
        float s  = v0 + v1 + v2;
        float sq = v0*v0 + v1*v1 + v2*v2;
        #pragma unroll
        for (int o = 16; o > 0; o >>= 1) {
            s  += __shfl_xor_sync(0xffffffffu, s,  o);
            sq += __shfl_xor_sync(0xffffffffu, sq, o);
        }
        const float mean = s * (1.f / 96.f);
        const float var  = sq * (1.f / 96.f) - mean * mean;
        const float rstd = rsqrtf(var + 1e-5f);
        sX[n*XP + lane]      = __float2bfloat16((v0 - mean) * rstd * n1g[lane]      + n1b[lane]);
        sX[n*XP + lane + 32] = __float2bfloat16((v1 - mean) * rstd * n1g[lane + 32] + n1b[lane + 32]);
        sX[n*XP + lane + 64] = __float2bfloat16((v2 - mean) * rstd * n1g[lane + 64] + n1b[lane + 64]);
    }
    // zero pad rows 49..63 of sX (all cols)
    for (int p = tid; p < (MP - NN) * XP; p += 256)
        sX[(NN + p / XP) * XP + (p % XP)] = __float2bfloat16(0.f);
    // ---- phase 0b: bias+mask table (bf16); padded m -> -30000 ----
    for (int p = tid; p < NHH * MP * BMP; p += 256) {
        const int h = p / (MP * BMP);
        const int r = p - h * (MP * BMP);
        const int n = r / BMP, m = r - n * BMP;
        float v = -30000.f;
        if (n < NN && m < NN)
            v = bias_table[rel_index[n*NN + m] * NHH + h] +
                attn_mask[((size_t)w2 * NN + n) * NN + m];
        sBM[p] = __float2bfloat16(v);
    }
    __syncthreads();

    // ---- phase 1: qkv GEMM, 2 chunks of 144 output rows ----
    const int rb  = warp & 3;       // row block (16 rows)
    const int m0  = rb * 16;
    const int nsb = warp >> 2;      // 0/1 -> 72-col sub-chunk
    for (int ch = 0; ch < 2; ch++) {
        for (int p = tid; p < 144*48; p += 256) {
            const int r = p / 48, c = (p % 48) * 2;
            const float2 wv = *reinterpret_cast<const float2*>(qkv_w + (ch*144 + r)*96 + c);
            *reinterpret_cast<__nv_bfloat162*>(&sW[r*XP + c]) = __floats2bfloat162_rn(wv.x, wv.y);
        }
        __syncthreads();
        float acc[9][4];
        #pragma unroll
        for (int t = 0; t < 9; t++) { acc[t][0]=0.f; acc[t][1]=0.f; acc[t][2]=0.f; acc[t][3]=0.f; }
        #pragma unroll
        for (int ks = 0; ks < 6; ks++) {
            const int k = ks*16 + 2*tig;
            uint32_t a[4];
            a[0] = *reinterpret_cast<const uint32_t*>(&sX[(m0 + gid    )*XP + k]);
            a[1] = *reinterpret_cast<const uint32_t*>(&sX[(m0 + gid + 8)*XP + k]);
            a[2] = *reinterpret_cast<const uint32_t*>(&sX[(m0 + gid    )*XP + k + 8]);
            a[3] = *reinterpret_cast<const uint32_t*>(&sX[(m0 + gid + 8)*XP + k + 8]);
            #pragma unroll
            for (int nt = 0; nt < 9; nt++) {
                const int n = nsb*72 + nt*8 + gid;
                uint32_t bb[2];
                bb[0] = *reinterpret_cast<const uint32_t*>(&sW[n*XP + k]);
                bb[1] = *reinterpret_cast<const uint32_t*>(&sW[n*XP + k + 8]);
                mma16816(acc[nt], a, bb);
            }
        }
        const int t0 = m0 + gid, t1 = m0 + gid + 8;
        #pragma unroll
        for (int nt = 0; nt < 9; nt++) {
            const int g = ch*144 + nsb*72 + nt*8 + 2*tig;
            const float b0 = qkv_b[g], b1 = qkv_b[g + 1];
            float v00 = acc[nt][0] + b0, v01 = acc[nt][1] + b1;
            float v10 = acc[nt][2] + b0, v11 = acc[nt][3] + b1;
            if (g < 96) {
                const float sc = 0.17677669529663687f;
                *reinterpret_cast<__nv_bfloat162*>(&sQ[t0*XP + g]) = __floats2bfloat162_rn(v00*sc, v01*sc);
                *reinterpret_cast<__nv_bfloat162*>(&sQ[t1*XP + g]) = __floats2bfloat162_rn(v10*sc, v11*sc);
            } else if (g < 192) {
                *reinterpret_cast<__nv_bfloat162*>(&sK[t0*XP + g - 96]) = __floats2bfloat162_rn(v00, v01);
                *reinterpret_cast<__nv_bfloat162*>(&sK[t1*XP + g - 96]) = __floats2bfloat162_rn(v10, v11);
            } else {
                const int d = g - 192;
                sVt[d*VTP + t0]     = __float2bfloat16(v00);
                sVt[(d+1)*VTP + t0] = __float2bfloat16(v01);
                sVt[d*VTP + t1]     = __float2bfloat16(v10);
                sVt[(d+1)*VTP + t1] = __float2bfloat16(v11);
            }
        }
        __syncthreads();
    }

    // stage proj weights now (sW free after last sync); used after next sync
    for (int p = tid; p < 96*48; p += 256) {
        const int r = p / 48, c = (p % 48) * 2;
        const float2 wv = *reinterpret_cast<const float2*>(proj_w + r*96 + c);
        *reinterpret_cast<__nv_bfloat162*>(&sW[r*XP + c]) = __floats2bfloat162_rn(wv.x, wv.y);
    }

    // ---- phase 2: per (head, rowblock): S=QK^T, +bias/mask, softmax, O=PV ----
    for (int task = warp; task < 12; task += 8) {
        const int h   = task >> 2;
        const int trb = task & 3;
        const int r0  = trb * 16;
        float sacc[8][4];
        #pragma unroll
        for (int t = 0; t < 8; t++) { sacc[t][0]=0.f; sacc[t][1]=0.f; sacc[t][2]=0.f; sacc[t][3]=0.f; }
        #pragma unroll
        for (int ks = 0; ks < 2; ks++) {
            const int k = h*32 + ks*16 + 2*tig;
            uint32_t a[4];
            a[0] = *reinterpret_cast<const uint32_t*>(&sQ[(r0 + gid    )*XP + k]);
            a[1] = *reinterpret_cast<const uint32_t*>(&sQ[(r0 + gid + 8)*XP + k]);
            a[2] = *reinterpret_cast<const uint32_t*>(&sQ[(r0 + gid    )*XP + k + 8]);
            a[3] = *reinterpret_cast<const uint32_t*>(&sQ[(r0 + gid + 8)*XP + k + 8]);
            #pragma unroll
            for (int nt = 0; nt < 8; nt++) {
                uint32_t bb[2];
                bb[0] = *reinterpret_cast<const uint32_t*>(&sK[(nt*8 + gid)*XP + k]);
                bb[1] = *reinterpret_cast<const uint32_t*>(&sK[(nt*8 + gid)*XP + k + 8]);
                mma16816(sacc[nt], a, bb);
            }
        }
        // add bias+mask
        const __nv_bfloat16* bm0 = sBM + (h*MP + r0 + gid    )*BMP;
        const __nv_bfloat16* bm1 = sBM + (h*MP + r0 + gid + 8)*BMP;
        #pragma unroll
        for (int nt = 0; nt < 8; nt++) {
            const int m = nt*8 + 2*tig;
            sacc[nt][0] += __bfloat162float(bm0[m]);
            sacc[nt][1] += __bfloat162float(bm0[m+1]);
            sacc[nt][2] += __bfloat162float(bm1[m]);
            sacc[nt][3] += __bfloat162float(bm1[m+1]);
        }
        // softmax rows r0+gid (vals [0],[1]) and r0+gid+8 (vals [2],[3]); row spread over tig quad
        float mx0 = -1e30f, mx1 = -1e30f;
        #pragma unroll
        for (int nt = 0; nt < 8; nt++) {
            mx0 = fmaxf(mx0, fmaxf(sacc[nt][0], sacc[nt][1]));
            mx1 = fmaxf(mx1, fmaxf(sacc[nt][2], sacc[nt][3]));
        }
        mx0 = fmaxf(mx0, __shfl_xor_sync(0xffffffffu, mx0, 1));
        mx0 = fmaxf(mx0, __shfl_xor_sync(0xffffffffu, mx0, 2));
        mx1 = fmaxf(mx1, __shfl_xor_sync(0xffffffffu, mx1, 1));
        mx1 = fmaxf(mx1, __shfl_xor_sync(0xffffffffu, mx1, 2));
        float sm0 = 0.f, sm1 = 0.f;
        #pragma unroll
        for (int nt = 0; nt < 8; nt++) {
            sacc[nt][0] = __expf(sacc[nt][0] - mx0);
            sacc[nt][1] = __expf(sacc[nt][1] - mx0);
            sacc[nt][2] = __expf(sacc[nt][2] - mx1);
            sacc[nt][3] = __expf(sacc[nt][3] - mx1);
            sm0 += sacc[nt][0] + sacc[nt][1];
            sm1 += sacc[nt][2] + sacc[nt][3];
        }
        sm0 += __shfl_xor_sync(0xffffffffu, sm0, 1);
        sm0 += __shfl_xor_sync(0xffffffffu, sm0, 2);
        sm1 += __shfl_xor_sync(0xffffffffu, sm1, 1);
        sm1 += __shfl_xor_sync(0xffffffffu, sm1, 2);
        const float iv0 = 1.f / sm0, iv1 = 1.f / sm1;
        // pack P into A-fragments (C layout == A layout under n->k reinterpretation)
        uint32_t pf[4][4];
        #pragma unroll
        for (int kc = 0; kc < 4; kc++) {
            pf[kc][0] = packbf(sacc[2*kc][0]*iv0,   sacc[2*kc][1]*iv0);
            pf[kc][1] = packbf(sacc[2*kc][2]*iv1,   sacc[2*kc][3]*iv1);
            pf[kc][2] = packbf(sacc[2*kc+1][0]*iv0, sacc[2*kc+1][1]*iv0);
            pf[kc][3] = packbf(sacc[2*kc+1][2]*iv1, sacc[2*kc+1][3]*iv1);
        }
        // O = P @ V  (V from transposed tile)
        float oacc[4][4];
        #pragma unroll
        for (int t = 0; t < 4; t++) { oacc[t][0]=0.f; oacc[t][1]=0.f; oacc[t][2]=0.f; oacc[t][3]=0.f; }
        #pragma unroll
        for (int kc = 0; kc < 4; kc++) {
            #pragma unroll
            for (int nt = 0; nt < 4; nt++) {
                uint32_t bb[2];
                bb[0] = *reinterpret_cast<const uint32_t*>(&sVt[(h*32 + nt*8 + gid)*VTP + kc*16 + 2*tig]);
                bb[1] = *reinterpret_cast<const uint32_t*>(&sVt[(h*32 + nt*8 + gid)*VTP + kc*16 + 2*tig + 8]);
                mma16816(oacc[nt], pf[kc], bb);
            }
        }
        // write attn output into sX (freed after qkv)
        #pragma unroll
        for (int nt = 0; nt < 4; nt++) {
            const int d = h*32 + nt*8 + 2*tig;
            *reinterpret_cast<__nv_bfloat162*>(&sX[(r0 + gid    )*XP + d]) =
                __floats2bfloat162_rn(oacc[nt][0], oacc[nt][1]);
            *reinterpret_cast<__nv_bfloat162*>(&sX[(r0 + gid + 8)*XP + d]) =
                __floats2bfloat162_rn(oacc[nt][2], oacc[nt][3]);
        }
    }
    __syncthreads();

    // ---- phase 3: proj + residual, scatter with reverse shift ----
    {
        const int nc = warp >> 2;   // 0/1 -> 48-col chunk
        float acc[6][4];
        #pragma unroll
        for (int t = 0; t < 6; t++) { acc[t][0]=0.f; acc[t][1]=0.f; acc[t][2]=0.f; acc[t][3]=0.f; }
        #pragma unroll
        for (int ks = 0; ks < 6; ks++) {
            const int k = ks*16 + 2*tig;
            uint32_t a[4];
            a[0] = *reinterpret_cast<const uint32_t*>(&sX[(m0 + gid    )*XP + k]);
            a[1] = *reinterpret_cast<const uint32_t*>(&sX[(m0 + gid + 8)*XP + k]);
            a[2] = *reinterpret_cast<const uint32_t*>(&sX[(m0 + gid    )*XP + k + 8]);
            a[3] = *reinterpret_cast<const uint32_t*>(&sX[(m0 + gid + 8)*XP + k + 8]);
            #pragma unroll
            for (int nt = 0; nt < 6; nt++) {
                const int n = nc*48 + nt*8 + gid;
                uint32_t bb[2];
                bb[0] = *reinterpret_cast<const uint32_t*>(&sW[n*XP + k]);
                bb[1] = *reinterpret_cast<const uint32_t*>(&sW[n*XP + k + 8]);
                mma16816(acc[nt], a, bb);
            }
        }
        #pragma unroll
        for (int rr = 0; rr < 2; rr++) {
            const int tok = m0 + gid + rr*8;
            if (tok < NN) {
                const int i = tok / WSZ, j = tok % WSZ;
                int oy = wh * WSZ + i + SHIFT; if (oy >= HH)  oy -= HH;
                int ox = ww * WSZ + j + SHIFT; if (ox >= WW2) ox -= WW2;
                const size_t rowb = ((size_t)(b * 12544 + oy * WW2 + ox)) * CC;
                #pragma unroll
                for (int nt = 0; nt < 6; nt++) {
                    const int g = nc*48 + nt*8 + 2*tig;
                    const float2 res = *reinterpret_cast<const float2*>(x + rowb + g);
                    float2 o2;
                    o2.x = acc[nt][rr*2 + 0] + proj_b[g]     + res.x;
                    o2.y = acc[nt][rr*2 + 1] + proj_b[g + 1] + res.y;
                    *reinterpret_cast<float2*>(g_x1 + rowb + g) = o2;
                }
            }
        }
    }
}

// ============================================================================
// MLP kernel: warp-level mma.sync bf16 (unchanged from round 13 - passing)
// ============================================================================
#define AP 104
#define HP 392
#define MSM_A 0
#define MSM_H (128*AP*2)
#define MSM_W (MSM_H + 128*HP*2)
#define MLP_SMEM_TOTAL (MSM_W + 384*AP*2)   // 206848 bytes

__global__ __launch_bounds__(256, 1)
void swin_mlp_mma(const float* __restrict__ n2g, const float* __restrict__ n2b,
                  const float* __restrict__ fc1w, const float* __restrict__ fc1b,
                  const float* __restrict__ fc2w, const float* __restrict__ fc2b,
                  float* __restrict__ out)
{
    extern __shared__ char smem[];
    __nv_bfloat16* sA = reinterpret_cast<__nv_bfloat16*>(smem + MSM_A);
    __nv_bfloat16* sH = reinterpret_cast<__nv_bfloat16*>(smem + MSM_H);
    __nv_bfloat16* sW = reinterpret_cast<__nv_bfloat16*>(smem + MSM_W);

    const int tid  = threadIdx.x;
    const int lane = tid & 31;
    const int warp = tid >> 5;
    const int gid  = lane >> 2;
    const int tig  = lane & 3;
    const int tok0 = blockIdx.x * 128;
    const int m0   = warp * 16;

    for (int n = warp; n < 128; n += 8) {
        const float* xp = g_x1 + (size_t)(tok0 + n) * CC;
        float v0 = xp[lane], v1 = xp[lane + 32], v2 = xp[lane + 64];
        float s  = v0 + v1 + v2;
        float sq = v0*v0 + v1*v1 + v2*v2;
        #pragma unroll
        for (int o = 16; o > 0; o >>= 1) {
            s  += __shfl_xor_sync(0xffffffffu, s,  o);
            sq += __shfl_xor_sync(0xffffffffu, sq, o);
        }
        const float mean = s * (1.f / 96.f);
        const float var  = sq * (1.f / 96.f) - mean * mean;
        const float rstd = rsqrtf(var + 1e-5f);
        sA[n*AP + lane]      = __float2bfloat16((v0 - mean) * rstd * n2g[lane]      + n2b[lane]);
        sA[n*AP + lane + 32] = __float2bfloat16((v1 - mean) * rstd * n2g[lane + 32] + n2b[lane + 32]);
        sA[n*AP + lane + 64] = __float2bfloat16((v2 - mean) * rstd * n2g[lane + 64] + n2b[lane + 64]);
    }
    for (int p = tid; p < 384*48; p += 256) {
        const int r = p / 48, c = (p % 48) * 2;
        const float2 wv = *reinterpret_cast<const float2*>(fc1w + r*96 + c);
        *reinterpret_cast<__nv_bfloat162*>(&sW[r*AP + c]) = __floats2bfloat162_rn(wv.x, wv.y);
    }
    __syncthreads();

    for (int nc = 0; nc < 3; nc++) {
        const int n0 = nc * 128;
        float acc[16][4];
        #pragma unroll
        for (int t = 0; t < 16; t++) {
            acc[t][0] = 0.f; acc[t][1] = 0.f; acc[t][2] = 0.f; acc[t][3] = 0.f;
        }
        #pragma unroll
        for (int ks = 0; ks < 6; ks++) {
            const int k = ks*16 + 2*tig;
            uint32_t a[4];
            a[0] = *reinterpret_cast<const uint32_t*>(&sA[(m0 + gid    )*AP + k]);
            a[1] = *reinterpret_cast<const uint32_t*>(&sA[(m0 + gid + 8)*AP + k]);
            a[2] = *reinterpret_cast<const uint32_t*>(&sA[(m0 + gid    )*AP + k + 8]);
            a[3] = *reinterpret_cast<const uint32_t*>(&sA[(m0 + gid + 8)*AP + k + 8]);
            #pragma unroll
            for (int nt = 0; nt < 16; nt++) {
                const int n = n0 + nt*8 + gid;
                uint32_t b[2];
                b[0] = *reinterpret_cast<const uint32_t*>(&sW[n*AP + k]);
                b[1] = *reinterpret_cast<const uint32_t*>(&sW[n*AP + k + 8]);
                mma16816(acc[nt], a, b);
            }
        }
        #pragma unroll
        for (int nt = 0; nt < 16; nt++) {
            const int n = n0 + nt*8 + 2*tig;
            const float b0 = fc1b[n], b1 = fc1b[n + 1];
            float h0 = acc[nt][0] + b0, h1 = acc[nt][1] + b1;
            float h2 = acc[nt][2] + b0, h3 = acc[nt][3] + b1;
            h0 = 0.5f * h0 * (1.f + erff(h0 * 0.70710678118654752f));
            h1 = 0.5f * h1 * (1.f + erff(h1 * 0.70710678118654752f));
            h2 = 0.5f * h2 * (1.f + erff(h2 * 0.70710678118654752f));
            h3 = 0.5f * h3 * (1.f + erff(h3 * 0.70710678118654752f));
            *reinterpret_cast<__nv_bfloat162*>(&sH[(m0 + gid    )*HP + n]) = __floats2bfloat162_rn(h0, h1);
            *reinterpret_cast<__nv_bfloat162*>(&sH[(m0 + gid + 8)*HP + n]) = __floats2bfloat162_rn(h2, h3);
        }
    }
    __syncthreads();

    for (int p = tid; p < 96*192; p += 256) {
        const int r = p / 192, c = (p % 192) * 2;
        const float2 wv = *reinterpret_cast<const float2*>(fc2w + r*384 + c);
        *reinterpret_cast<__nv_bfloat162*>(&sW[r*HP + c]) = __floats2bfloat162_rn(wv.x, wv.y);
    }
    __syncthreads();

    {
        float acc[12][4];
        #pragma unroll
        for (int t = 0; t < 12; t++) {
            acc[t][0] = 0.f; acc[t][1] = 0.f; acc[t][2] = 0.f; acc[t][3] = 0.f;
        }
        for (int ks = 0; ks < 24; ks++) {
            const int k = ks*16 + 2*tig;
            uint32_t a[4];
            a[0] = *reinterpret_cast<const uint32_t*>(&sH[(m0 + gid    )*HP + k]);
            a[1] = *reinterpret_cast<const uint32_t*>(&sH[(m0 + gid + 8)*HP + k]);
            a[2] = *reinterpret_cast<const uint32_t*>(&sH[(m0 + gid    )*HP + k + 8]);
            a[3] = *reinterpret_cast<const uint32_t*>(&sH[(m0 + gid + 8)*HP + k + 8]);
            #pragma unroll
            for (int nt = 0; nt < 12; nt++) {
                const int n = nt*8 + gid;
                uint32_t b[2];
                b[0] = *reinterpret_cast<const uint32_t*>(&sW[n*HP + k]);
                b[1] = *reinterpret_cast<const uint32_t*>(&sW[n*HP + k + 8]);
                mma16816(acc[nt], a, b);
            }
        }
        #pragma unroll
        for (int nt = 0; nt < 12; nt++) {
            const int n = nt*8 + 2*tig;
            const float b0 = fc2b[n], b1 = fc2b[n + 1];
            const size_t r0 = (size_t)(tok0 + m0 + gid)     * CC + n;
            const size_t r1 = (size_t)(tok0 + m0 + gid + 8) * CC + n;
            const float2 x0 = *reinterpret_cast<const float2*>(g_x1 + r0);
            const float2 x1 = *reinterpret_cast<const float2*>(g_x1 + r1);
            float2 o0, o1;
            o0.x = acc[nt][0] + b0 + x0.x;  o0.y = acc[nt][1] + b1 + x0.y;
            o1.x = acc[nt][2] + b0 + x1.x;  o1.y = acc[nt][3] + b1 + x1.y;
            *reinterpret_cast<float2*>(out + r0) = o0;
            *reinterpret_cast<float2*>(out + r1) = o1;
        }
    }
}

extern "C" void kernel_launch(void* const* d_in, const int* in_sizes, int n_in,
                              void* d_out, int out_size)
{
    const float* x          = (const float*)d_in[0];
    const float* attn_mask  = (const float*)d_in[1];
    const int*   rel_index  = (const int*)  d_in[2];
    const float* n1g        = (const float*)d_in[3];
    const float* n1b        = (const float*)d_in[4];
    const float* qkv_w      = (const float*)d_in[5];
    const float* qkv_b      = (const float*)d_in[6];
    const float* proj_w     = (const float*)d_in[7];
    const float* proj_b     = (const float*)d_in[8];
    const float* bias_table = (const float*)d_in[9];
    const float* n2g        = (const float*)d_in[10];
    const float* n2b        = (const float*)d_in[11];
    const float* fc1w       = (const float*)d_in[12];
    const float* fc1b       = (const float*)d_in[13];
    const float* fc2w       = (const float*)d_in[14];
    const float* fc2b       = (const float*)d_in[15];
    float* out = (float*)d_out;

    cudaFuncSetAttribute(swin_attn_mma, cudaFuncAttributeMaxDynamicSharedMemorySize,
                         (int)ATT_SMEM_BYTES);
    cudaFuncSetAttribute(swin_mlp_mma, cudaFuncAttributeMaxDynamicSharedMemorySize,
                         (int)MLP_SMEM_TOTAL);

    swin_attn_mma<<<BB * NWIN, 256, ATT_SMEM_BYTES>>>(
        x, attn_mask, rel_index, n1g, n1b, qkv_w, qkv_b, proj_w, proj_b, bias_table);
    swin_mlp_mma<<<TOK / 128, 256, MLP_SMEM_TOTAL>>>(
        n2g, n2b, fc1w, fc1b, fc2w, fc2b, out);
}